// round 9
// baseline (speedup 1.0000x reference)
#include <cuda_runtime.h>
#include <cuda_fp16.h>
#include <math.h>
#include <stdint.h>

#define N_TOK 4096      // B*T
#define DDIM  1024
#define HDIM  4096
#define NEXP  8
#define NSLOT (N_TOK * 2)

// ---------------- scratch (static device globals; no cudaMalloc) ----------
__device__ __half g_hh[(size_t)NSLOT * HDIM];         // 64 MB : gelu out (fp16)
__device__ float  g_eo[(size_t)NSLOT * DDIM];         // 32 MB : expert out (fp32)
__device__ __half g_xh[(size_t)N_TOK * DDIM];         //  8 MB : x (fp16)
__device__ __half g_w1h[(size_t)NEXP * DDIM * HDIM];  // 64 MB : W1 fp16
__device__ __half g_w2h[(size_t)NEXP * DDIM * HDIM];  // 64 MB : W2 fp16
__device__ int   g_perm[NSLOT];
__device__ int   g_slot_of[NSLOT];
__device__ int   g_tope[NSLOT];
__device__ float g_topw[NSLOT];
__device__ int   g_cnt[NEXP];
__device__ int   g_off[NEXP];
__device__ int   g_cur[NEXP];

// ======================= PTX helpers (compute_103-safe) ====================
__device__ __forceinline__ uint32_t smem_u32(const void* p) {
    uint32_t a;
    asm("{ .reg .u64 t; cvta.to.shared.u64 t, %1; cvt.u32.u64 %0, t; }"
        : "=r"(a) : "l"(p));
    return a;
}
__device__ __forceinline__ void cp_async16(uint32_t dst, const void* src, uint32_t sz) {
    asm volatile("cp.async.ca.shared.global [%0], [%1], 16, %2;"
                 :: "r"(dst), "l"(src), "r"(sz) : "memory");
}
#define CP_COMMIT() asm volatile("cp.async.commit_group;" ::: "memory")
#define CP_WAIT(n)  asm volatile("cp.async.wait_group %0;" :: "n"(n) : "memory")

__device__ __forceinline__ void ldsm_x4(uint32_t* r, uint32_t addr) {
    asm volatile("ldmatrix.sync.aligned.m8n8.x4.shared.b16 {%0,%1,%2,%3}, [%4];"
                 : "=r"(r[0]), "=r"(r[1]), "=r"(r[2]), "=r"(r[3]) : "r"(addr));
}
__device__ __forceinline__ void ldsm_x4_t(uint32_t* r, uint32_t addr) {
    asm volatile("ldmatrix.sync.aligned.m8n8.x4.trans.shared.b16 {%0,%1,%2,%3}, [%4];"
                 : "=r"(r[0]), "=r"(r[1]), "=r"(r[2]), "=r"(r[3]) : "r"(addr));
}
__device__ __forceinline__ void mma_f16(float* d, const uint32_t* a,
                                        uint32_t b0, uint32_t b1) {
    asm volatile(
        "mma.sync.aligned.m16n8k16.row.col.f32.f16.f16.f32 "
        "{%0,%1,%2,%3}, {%4,%5,%6,%7}, {%8,%9}, {%0,%1,%2,%3};"
        : "+f"(d[0]), "+f"(d[1]), "+f"(d[2]), "+f"(d[3])
        : "r"(a[0]), "r"(a[1]), "r"(a[2]), "r"(a[3]), "r"(b0), "r"(b1));
}

// ======================= small kernels ======================================
__global__ void reset_kernel() {
    int i = threadIdx.x;
    if (i < NEXP) { g_cnt[i] = 0; g_cur[i] = 0; }
}

__global__ void gate_kernel(const float* __restrict__ x,
                            const float* __restrict__ Wg,
                            const float* __restrict__ bg) {
    int t = blockIdx.x;
    int lane = threadIdx.x;
    const float* xr = x + (size_t)t * DDIM;
    float p[NEXP];
#pragma unroll
    for (int e = 0; e < NEXP; e++) p[e] = 0.f;
    for (int d = lane; d < DDIM; d += 32) {
        float xv = xr[d];
        const float4* w4 = reinterpret_cast<const float4*>(Wg + (size_t)d * NEXP);
        float4 a = w4[0], b = w4[1];
        p[0] += xv * a.x; p[1] += xv * a.y; p[2] += xv * a.z; p[3] += xv * a.w;
        p[4] += xv * b.x; p[5] += xv * b.y; p[6] += xv * b.z; p[7] += xv * b.w;
    }
#pragma unroll
    for (int off = 16; off; off >>= 1)
#pragma unroll
        for (int e = 0; e < NEXP; e++)
            p[e] += __shfl_xor_sync(0xffffffffu, p[e], off);
    if (lane == 0) {
#pragma unroll
        for (int e = 0; e < NEXP; e++) p[e] += bg[e];
        int i0 = 0;
#pragma unroll
        for (int e = 1; e < NEXP; e++) if (p[e] > p[i0]) i0 = e;
        int i1 = (i0 == 0) ? 1 : 0;
#pragma unroll
        for (int e = 0; e < NEXP; e++)
            if (e != i0 && p[e] > p[i1]) i1 = e;
        float e1 = expf(p[i1] - p[i0]);
        float w0 = 1.0f / (1.0f + e1);
        float w1 = e1 / (1.0f + e1);
        g_tope[t * 2 + 0] = i0;  g_tope[t * 2 + 1] = i1;
        g_topw[t * 2 + 0] = w0;  g_topw[t * 2 + 1] = w1;
        atomicAdd(&g_cnt[i0], 1);
        atomicAdd(&g_cnt[i1], 1);
    }
}

__global__ void offsets_kernel() {
    if (threadIdx.x == 0) {
        int acc = 0;
        for (int e = 0; e < NEXP; e++) { g_off[e] = acc; acc += g_cnt[e]; }
    }
}

__global__ void scatter_kernel() {
    int t = blockIdx.x * blockDim.x + threadIdx.x;
    if (t >= N_TOK) return;
#pragma unroll
    for (int k = 0; k < 2; k++) {
        int e = g_tope[t * 2 + k];
        int pos = g_off[e] + atomicAdd(&g_cur[e], 1);
        g_perm[pos] = t;
        g_slot_of[t * 2 + k] = pos;
    }
}

// ---------------- fp32 -> fp16 elementwise (8 elems/thread) ----------------
__global__ void conv_half_kernel(const float* __restrict__ in,
                                 __half* __restrict__ out) {
    size_t i = (size_t)(blockIdx.x * blockDim.x + threadIdx.x) * 8;
    float4 v0 = *reinterpret_cast<const float4*>(in + i);
    float4 v1 = *reinterpret_cast<const float4*>(in + i + 4);
    __half2 h[4];
    h[0] = __floats2half2_rn(v0.x, v0.y);
    h[1] = __floats2half2_rn(v0.z, v0.w);
    h[2] = __floats2half2_rn(v1.x, v1.y);
    h[3] = __floats2half2_rn(v1.z, v1.w);
    *reinterpret_cast<uint4*>(out + i) = *reinterpret_cast<uint4*>(h);
}

// ======================= fp16 mma.sync grouped GEMM =========================
// Template tile: MTILE x NTILE, 8 warps (2m x 4n), warp tile MTILE/2 x NTILE/4.
// A smem: [MTILE m][64 k] (128B rows), B smem: [64 k][NTILE n] (NTILE*2 B rows),
// XOR-granule swizzle, all fragments via ldmatrix, 3-stage cp.async,
// fragment double-buffering across the 4 k16 sub-steps.
template <int KDIM, int MTILE, int NTILE, bool GATHER, bool DOGELU, typename OutT>
__global__ __launch_bounds__(256) void moe_gemm(
    const __half* __restrict__ Ah, const __half* __restrict__ Bh,
    const float* __restrict__ bias, OutT* __restrict__ Out, int Ntot) {
    constexpr int ASTG = MTILE * 128;       // bytes per A stage
    constexpr int BROW = NTILE * 2;         // bytes per B k-row
    constexpr int BSTG = 64 * BROW;         // bytes per B stage
    constexpr int OFF_A = 1024;
    constexpr int OFF_B = OFF_A + 3 * ASTG;
    constexpr int MI = MTILE / 32;          // m16 tiles per warp
    constexpr int NQ = NTILE / 64;          // n16 tiles per warp
    constexpr int NI = 2 * NQ;              // n8 acc tiles per warp
    constexpr int NG = NTILE / 32;          // B granule-pairs per warp
    constexpr int NC = KDIM / 64;

    extern __shared__ char smem[];
    const int e = blockIdx.z;
    const int cnt = g_cnt[e];
    const int m0 = blockIdx.x * MTILE;
    if (m0 >= cnt) return;
    const int off = g_off[e];
    const int n0 = blockIdx.y * NTILE;
    const __half* Bte = Bh + (size_t)e * KDIM * Ntot;   // [K][Ntot]

    const uint32_t sb = smem_u32(smem);
    const int tid = threadIdx.x;
    const int wid = tid >> 5, lane = tid & 31;
    const int wm = wid & 1, wn = wid >> 1;
    const int m_base = wm * (MTILE / 2), n_base = wn * (NTILE / 4);

    int* rowtok = (int*)smem;
    if (GATHER && tid < MTILE) {
        int r = m0 + tid;
        rowtok[tid] = (r < cnt) ? g_perm[off + r] : -1;
    }
    __syncthreads();

    auto load_chunk = [&](int c) {
        const int s = c % 3;
        const int k0 = c * 64;
        const uint32_t Abs = sb + OFF_A + s * ASTG;
        const uint32_t Bbs = sb + OFF_B + s * BSTG;
#pragma unroll
        for (int f = 0; f < MTILE / 32; f++) {
            int id = tid + f * 256;
            int row = id >> 3, g = id & 7;
            uint32_t sz = 16;
            const char* src;
            if (GATHER) {
                int tok = rowtok[row];
                if (tok < 0) { sz = 0; tok = 0; }
                src = (const char*)(Ah + (size_t)tok * KDIM + k0) + g * 16;
            } else {
                int mr = m0 + row;
                if (mr >= cnt) { sz = 0; mr = 0; }
                src = (const char*)(Ah + (size_t)(off + mr) * KDIM + k0) + g * 16;
            }
            cp_async16(Abs + row * 128 + ((g ^ (row & 7)) << 4), src, sz);
        }
#pragma unroll
        for (int f = 0; f < NTILE / 32; f++) {
            int id = tid + f * 256;
            int krow = id / (NTILE / 8), g = id % (NTILE / 8);
            const char* src =
                (const char*)(Bte + (size_t)(k0 + krow) * Ntot + n0) + g * 16;
            cp_async16(Bbs + krow * BROW + ((g ^ (krow & 7)) << 4), src, 16);
        }
        CP_COMMIT();
    };

    float acc[MI][NI][4];
#pragma unroll
    for (int mi = 0; mi < MI; mi++)
#pragma unroll
        for (int ni = 0; ni < NI; ni++)
#pragma unroll
            for (int q = 0; q < 4; q++) acc[mi][ni][q] = 0.f;

    load_chunk(0);
    load_chunk(1);

    const int rowsel = ((lane >> 3) & 1) * 8 + (lane & 7);
    const int gsel = (lane >> 4);
    const int bksel = lane & 15;
    const int bgsel = lane >> 4;

    uint32_t afr[2][MI][4];
    uint32_t bfr[2][NQ][4];

#pragma unroll 1
    for (int c = 0; c < NC; c++) {
        if (c + 1 < NC) { CP_WAIT(1); }
        else            { CP_WAIT(0); }
        __syncthreads();
        if (c + 2 < NC) load_chunk(c + 2);

        const uint32_t Abs = sb + OFF_A + (c % 3) * ASTG;
        const uint32_t Bbs = sb + OFF_B + (c % 3) * BSTG;

        auto ld_frags = [&](int ks, int buf) {
            const int ga = ks * 2 + gsel;
#pragma unroll
            for (int mi = 0; mi < MI; mi++) {
                int row = m_base + mi * 16 + rowsel;
                ldsm_x4(afr[buf][mi], Abs + row * 128 + ((ga ^ (row & 7)) << 4));
            }
            const int krow = ks * 16 + bksel;
#pragma unroll
            for (int nq = 0; nq < NQ; nq++) {
                int g = wn * NG + nq * 2 + bgsel;
                ldsm_x4_t(bfr[buf][nq], Bbs + krow * BROW + ((g ^ (krow & 7)) << 4));
            }
        };

        ld_frags(0, 0);
#pragma unroll
        for (int ks = 0; ks < 4; ks++) {
            if (ks < 3) ld_frags(ks + 1, (ks + 1) & 1);
            const int b = ks & 1;
#pragma unroll
            for (int mi = 0; mi < MI; mi++)
#pragma unroll
                for (int nq = 0; nq < NQ; nq++) {
                    mma_f16(acc[mi][2 * nq + 0], afr[b][mi], bfr[b][nq][0], bfr[b][nq][1]);
                    mma_f16(acc[mi][2 * nq + 1], afr[b][mi], bfr[b][nq][2], bfr[b][nq][3]);
                }
        }
        __syncthreads();
    }

    // ---- epilogue: bias (+gelu) + store ----
    const int lr = lane >> 2;
    const int lc = (lane & 3) * 2;
    float2 bv[NI];
#pragma unroll
    for (int ni = 0; ni < NI; ni++) {
        int col = n0 + n_base + ni * 8 + lc;
        const float* bp = bias + (size_t)e * Ntot + col;
        bv[ni] = make_float2(bp[0], bp[1]);
    }
#pragma unroll
    for (int mi = 0; mi < MI; mi++) {
        int r0 = m0 + m_base + mi * 16 + lr;
        int r1 = r0 + 8;
        bool v0 = r0 < cnt, v1 = r1 < cnt;
        OutT* o0 = Out + (size_t)(off + r0) * Ntot + n0 + n_base + lc;
        OutT* o1 = Out + (size_t)(off + r1) * Ntot + n0 + n_base + lc;
#pragma unroll
        for (int ni = 0; ni < NI; ni++) {
            if (v0) {
                float x0 = acc[mi][ni][0] + bv[ni].x;
                float x1 = acc[mi][ni][1] + bv[ni].y;
                if (DOGELU) { x0 = x0 * normcdff(x0); x1 = x1 * normcdff(x1); }
                if (sizeof(OutT) == 2)
                    *reinterpret_cast<__half2*>(o0 + ni * 8) = __floats2half2_rn(x0, x1);
                else
                    *reinterpret_cast<float2*>(o0 + ni * 8) = make_float2(x0, x1);
            }
            if (v1) {
                float x2 = acc[mi][ni][2] + bv[ni].x;
                float x3 = acc[mi][ni][3] + bv[ni].y;
                if (DOGELU) { x2 = x2 * normcdff(x2); x3 = x3 * normcdff(x3); }
                if (sizeof(OutT) == 2)
                    *reinterpret_cast<__half2*>(o1 + ni * 8) = __floats2half2_rn(x2, x3);
                else
                    *reinterpret_cast<float2*>(o1 + ni * 8) = make_float2(x2, x3);
            }
        }
    }
}

// ---------------- combine: out[t] = w0*eo[s0] + w1*eo[s1] ------------------
__global__ void combine_kernel(float* __restrict__ out) {
    int t = blockIdx.x;
    int s0 = g_slot_of[t * 2 + 0], s1 = g_slot_of[t * 2 + 1];
    float w0 = g_topw[t * 2 + 0], w1 = g_topw[t * 2 + 1];
    const float4* a = reinterpret_cast<const float4*>(g_eo + (size_t)s0 * DDIM);
    const float4* b = reinterpret_cast<const float4*>(g_eo + (size_t)s1 * DDIM);
    float4* o = reinterpret_cast<float4*>(out + (size_t)t * DDIM);
    for (int i = threadIdx.x; i < DDIM / 4; i += blockDim.x) {
        float4 va = a[i], vb = b[i];
        o[i] = make_float4(w0 * va.x + w1 * vb.x, w0 * va.y + w1 * vb.y,
                           w0 * va.z + w1 * vb.z, w0 * va.w + w1 * vb.w);
    }
}

// ---------------- launch ----------------------------------------------------
extern "C" void kernel_launch(void* const* d_in, const int* in_sizes, int n_in,
                              void* d_out, int out_size) {
    const float* x  = (const float*)d_in[0];
    const float* Wg = (const float*)d_in[1];
    const float* bg = (const float*)d_in[2];
    const float* W1 = (const float*)d_in[3];
    const float* b1 = (const float*)d_in[4];
    const float* W2 = (const float*)d_in[5];
    const float* b2 = (const float*)d_in[6];
    float* out = (float*)d_out;

    void *p_hh, *p_eo, *p_xh, *p_w1h, *p_w2h;
    cudaGetSymbolAddress(&p_hh,  g_hh);
    cudaGetSymbolAddress(&p_eo,  g_eo);
    cudaGetSymbolAddress(&p_xh,  g_xh);
    cudaGetSymbolAddress(&p_w1h, g_w1h);
    cudaGetSymbolAddress(&p_w2h, g_w2h);

    // GEMM1: 128x256 tiles.  GEMM2: 64x128 tiles (fine-grain, 2 CTAs/SM).
    constexpr int SMB1 = 1024 + 3 * (128 * 128) + 3 * (256 * 128);  // 148480
    constexpr int SMB2 = 1024 + 3 * (64 * 128) + 3 * (128 * 128);   //  74752
    cudaFuncSetAttribute(moe_gemm<DDIM, 128, 256, true,  true,  __half>,
                         cudaFuncAttributeMaxDynamicSharedMemorySize, SMB1);
    cudaFuncSetAttribute(moe_gemm<HDIM, 64, 128, false, false, float>,
                         cudaFuncAttributeMaxDynamicSharedMemorySize, SMB2);

    reset_kernel<<<1, 32>>>();
    gate_kernel<<<N_TOK, 32>>>(x, Wg, bg);
    offsets_kernel<<<1, 32>>>();
    scatter_kernel<<<(N_TOK + 255) / 256, 256>>>();
    conv_half_kernel<<<((size_t)N_TOK * DDIM / 8) / 256, 256>>>(x, (__half*)p_xh);
    conv_half_kernel<<<((size_t)NEXP * DDIM * HDIM / 8) / 256, 256>>>(W1, (__half*)p_w1h);
    conv_half_kernel<<<((size_t)NEXP * DDIM * HDIM / 8) / 256, 256>>>(W2, (__half*)p_w2h);
    // GEMM1: h = fp16(gelu(x[perm] @ W1 + b1))   K=1024, N=4096
    moe_gemm<DDIM, 128, 256, true, true, __half>
        <<<dim3(32, HDIM / 256, NEXP), 256, SMB1>>>(
        (const __half*)p_xh, (const __half*)p_w1h, b1, (__half*)p_hh, HDIM);
    // GEMM2: eo = h @ W2 + b2                    K=4096, N=1024
    moe_gemm<HDIM, 64, 128, false, false, float>
        <<<dim3(64, DDIM / 128, NEXP), 256, SMB2>>>(
        (const __half*)p_hh, (const __half*)p_w2h, b2, (float*)p_eo, DDIM);
    combine_kernel<<<N_TOK, 256>>>(out);
}

// round 10
// speedup vs baseline: 1.7645x; 1.7645x over previous
#include <cuda_runtime.h>
#include <cuda_fp16.h>
#include <math.h>
#include <stdint.h>

#define N_TOK 4096      // B*T
#define DDIM  1024
#define HDIM  4096
#define NEXP  8
#define NSLOT (N_TOK * 2)

// ---------------- scratch (static device globals; no cudaMalloc) ----------
__device__ __half g_hh[(size_t)NSLOT * HDIM];         // 64 MB : gelu out (fp16)
__device__ float  g_eo[(size_t)NSLOT * DDIM];         // 32 MB : expert out (fp32)
__device__ __half g_xh[(size_t)N_TOK * DDIM];         //  8 MB : x (fp16)
__device__ __half g_w1h[(size_t)NEXP * DDIM * HDIM];  // 64 MB : W1 fp16
__device__ __half g_w2h[(size_t)NEXP * DDIM * HDIM];  // 64 MB : W2 fp16
__device__ int   g_perm[NSLOT];
__device__ int   g_slot_of[NSLOT];
__device__ int   g_tope[NSLOT];
__device__ float g_topw[NSLOT];
__device__ int   g_cnt[NEXP];
__device__ int   g_off[NEXP];
__device__ int   g_cur[NEXP];

// ======================= PTX helpers (compute_103-safe) ====================
__device__ __forceinline__ uint32_t smem_u32(const void* p) {
    uint32_t a;
    asm("{ .reg .u64 t; cvta.to.shared.u64 t, %1; cvt.u32.u64 %0, t; }"
        : "=r"(a) : "l"(p));
    return a;
}
__device__ __forceinline__ void cp_async16(uint32_t dst, const void* src, uint32_t sz) {
    asm volatile("cp.async.ca.shared.global [%0], [%1], 16, %2;"
                 :: "r"(dst), "l"(src), "r"(sz) : "memory");
}
#define CP_COMMIT() asm volatile("cp.async.commit_group;" ::: "memory")
#define CP_WAIT(n)  asm volatile("cp.async.wait_group %0;" :: "n"(n) : "memory")

__device__ __forceinline__ void ldsm_x4(uint32_t* r, uint32_t addr) {
    asm volatile("ldmatrix.sync.aligned.m8n8.x4.shared.b16 {%0,%1,%2,%3}, [%4];"
                 : "=r"(r[0]), "=r"(r[1]), "=r"(r[2]), "=r"(r[3]) : "r"(addr));
}
__device__ __forceinline__ void ldsm_x4_t(uint32_t* r, uint32_t addr) {
    asm volatile("ldmatrix.sync.aligned.m8n8.x4.trans.shared.b16 {%0,%1,%2,%3}, [%4];"
                 : "=r"(r[0]), "=r"(r[1]), "=r"(r[2]), "=r"(r[3]) : "r"(addr));
}
__device__ __forceinline__ void mma_f16(float* d, const uint32_t* a,
                                        uint32_t b0, uint32_t b1) {
    asm volatile(
        "mma.sync.aligned.m16n8k16.row.col.f32.f16.f16.f32 "
        "{%0,%1,%2,%3}, {%4,%5,%6,%7}, {%8,%9}, {%0,%1,%2,%3};"
        : "+f"(d[0]), "+f"(d[1]), "+f"(d[2]), "+f"(d[3])
        : "r"(a[0]), "r"(a[1]), "r"(a[2]), "r"(a[3]), "r"(b0), "r"(b1));
}
// exact gelu via erff (no erfc range-reduction/exp path)
__device__ __forceinline__ float gelu_erf(float v) {
    return 0.5f * v * (1.0f + erff(v * 0.70710678118654752f));
}

// ======================= small kernels ======================================
__global__ void reset_kernel() {
    int i = threadIdx.x;
    if (i < NEXP) { g_cnt[i] = 0; g_cur[i] = 0; }
}

__global__ void gate_kernel(const float* __restrict__ x,
                            const float* __restrict__ Wg,
                            const float* __restrict__ bg) {
    int t = blockIdx.x;
    int lane = threadIdx.x;
    const float* xr = x + (size_t)t * DDIM;
    float p[NEXP];
#pragma unroll
    for (int e = 0; e < NEXP; e++) p[e] = 0.f;
    for (int d = lane; d < DDIM; d += 32) {
        float xv = xr[d];
        const float4* w4 = reinterpret_cast<const float4*>(Wg + (size_t)d * NEXP);
        float4 a = w4[0], b = w4[1];
        p[0] += xv * a.x; p[1] += xv * a.y; p[2] += xv * a.z; p[3] += xv * a.w;
        p[4] += xv * b.x; p[5] += xv * b.y; p[6] += xv * b.z; p[7] += xv * b.w;
    }
#pragma unroll
    for (int off = 16; off; off >>= 1)
#pragma unroll
        for (int e = 0; e < NEXP; e++)
            p[e] += __shfl_xor_sync(0xffffffffu, p[e], off);
    if (lane == 0) {
#pragma unroll
        for (int e = 0; e < NEXP; e++) p[e] += bg[e];
        int i0 = 0;
#pragma unroll
        for (int e = 1; e < NEXP; e++) if (p[e] > p[i0]) i0 = e;
        int i1 = (i0 == 0) ? 1 : 0;
#pragma unroll
        for (int e = 0; e < NEXP; e++)
            if (e != i0 && p[e] > p[i1]) i1 = e;
        float e1 = expf(p[i1] - p[i0]);
        float w0 = 1.0f / (1.0f + e1);
        float w1 = e1 / (1.0f + e1);
        g_tope[t * 2 + 0] = i0;  g_tope[t * 2 + 1] = i1;
        g_topw[t * 2 + 0] = w0;  g_topw[t * 2 + 1] = w1;
        atomicAdd(&g_cnt[i0], 1);
        atomicAdd(&g_cnt[i1], 1);
    }
}

__global__ void offsets_kernel() {
    if (threadIdx.x == 0) {
        int acc = 0;
        for (int e = 0; e < NEXP; e++) { g_off[e] = acc; acc += g_cnt[e]; }
    }
}

__global__ void scatter_kernel() {
    int t = blockIdx.x * blockDim.x + threadIdx.x;
    if (t >= N_TOK) return;
#pragma unroll
    for (int k = 0; k < 2; k++) {
        int e = g_tope[t * 2 + k];
        int pos = g_off[e] + atomicAdd(&g_cur[e], 1);
        g_perm[pos] = t;
        g_slot_of[t * 2 + k] = pos;
    }
}

// ---------------- fp32 -> fp16 elementwise (8 elems/thread) ----------------
__global__ void conv_half_kernel(const float* __restrict__ in,
                                 __half* __restrict__ out) {
    size_t i = (size_t)(blockIdx.x * blockDim.x + threadIdx.x) * 8;
    float4 v0 = *reinterpret_cast<const float4*>(in + i);
    float4 v1 = *reinterpret_cast<const float4*>(in + i + 4);
    __half2 h[4];
    h[0] = __floats2half2_rn(v0.x, v0.y);
    h[1] = __floats2half2_rn(v0.z, v0.w);
    h[2] = __floats2half2_rn(v1.x, v1.y);
    h[3] = __floats2half2_rn(v1.z, v1.w);
    *reinterpret_cast<uint4*>(out + i) = *reinterpret_cast<uint4*>(h);
}

// ======================= fp16 mma.sync grouped GEMM =========================
// CTA tile 128(M) x 256(N), k-chunk 64, 8 warps (2m x 4n), warp tile 64x64.
// A smem: [128 m][64 k] (128B rows), B smem: [64 k][256 n] (512B rows),
// XOR-granule swizzle, all fragments via ldmatrix.
// 4-stage cp.async pipeline, ONE barrier per chunk:
//   CP_WAIT(chunk c) ; __syncthreads() ; load_chunk(c+3) ; compute chunk c.
#define ASTAGE_B 16384
#define BSTAGE_B 32768
#define OFF_A    1024
#define OFF_B    (OFF_A + 4 * ASTAGE_B)        // 66560
#define SM_BYTES (OFF_B + 4 * BSTAGE_B)        // 197632

template <int KDIM, bool GATHER, bool DOGELU, typename OutT>
__global__ __launch_bounds__(256) void moe_gemm(
    const __half* __restrict__ Ah, const __half* __restrict__ Bh,
    const float* __restrict__ bias, OutT* __restrict__ Out, int Ntot) {
    extern __shared__ char smem[];
    const int e = blockIdx.z;
    const int cnt = g_cnt[e];
    const int m0 = blockIdx.x * 128;
    if (m0 >= cnt) return;
    const int off = g_off[e];
    const int n0 = blockIdx.y * 256;
    const __half* Bte = Bh + (size_t)e * KDIM * Ntot;   // [K][Ntot]

    const uint32_t sb = smem_u32(smem);
    const int tid = threadIdx.x;
    const int wid = tid >> 5, lane = tid & 31;
    const int wm = wid & 1, wn = wid >> 1;
    const int m_base = wm * 64, n_base = wn * 64;

    int* rowtok = (int*)smem;
    if (GATHER && tid < 128) {
        int r = m0 + tid;
        rowtok[tid] = (r < cnt) ? g_perm[off + r] : -1;
    }
    __syncthreads();

    constexpr int NC = KDIM / 64;

    auto load_chunk = [&](int c) {
        const int s = c & 3;
        const int k0 = c * 64;
        const uint32_t Abs = sb + OFF_A + s * ASTAGE_B;
        const uint32_t Bbs = sb + OFF_B + s * BSTAGE_B;
#pragma unroll
        for (int f = 0; f < 4; f++) {
            int id = tid + f * 256;
            int row = id >> 3, g = id & 7;
            uint32_t sz = 16;
            const char* src;
            if (GATHER) {
                int tok = rowtok[row];
                if (tok < 0) { sz = 0; tok = 0; }
                src = (const char*)(Ah + (size_t)tok * KDIM + k0) + g * 16;
            } else {
                int mr = m0 + row;
                if (mr >= cnt) { sz = 0; mr = 0; }
                src = (const char*)(Ah + (size_t)(off + mr) * KDIM + k0) + g * 16;
            }
            cp_async16(Abs + row * 128 + ((g ^ (row & 7)) << 4), src, sz);
        }
#pragma unroll
        for (int f = 0; f < 8; f++) {
            int id = tid + f * 256;
            int krow = id >> 5, g = id & 31;
            const char* src =
                (const char*)(Bte + (size_t)(k0 + krow) * Ntot + n0) + g * 16;
            cp_async16(Bbs + krow * 512 + ((g ^ (krow & 7)) << 4), src, 16);
        }
        CP_COMMIT();
    };

    float acc[4][8][4];
#pragma unroll
    for (int mi = 0; mi < 4; mi++)
#pragma unroll
        for (int ni = 0; ni < 8; ni++)
#pragma unroll
            for (int q = 0; q < 4; q++) acc[mi][ni][q] = 0.f;

    load_chunk(0);
    load_chunk(1);
    load_chunk(2);

    const int rowsel = ((lane >> 3) & 1) * 8 + (lane & 7);
    const int gsel = (lane >> 4);
    const int bksel = lane & 15;
    const int bgsel = lane >> 4;

#pragma unroll 1
    for (int c = 0; c < NC; c++) {
        // 1) chunk c's cp.async group complete (<=2 younger groups may remain)
        if (c + 2 < NC)      { CP_WAIT(2); }
        else if (c + 1 < NC) { CP_WAIT(1); }
        else                 { CP_WAIT(0); }
        // 2) all warps see chunk c; all warps done reading stage (c-1)&3
        __syncthreads();
        // 3) safe to overwrite stage (c+3)&3 == (c-1)&3
        if (c + 3 < NC) load_chunk(c + 3);

        const uint32_t Abs = sb + OFF_A + (c & 3) * ASTAGE_B;
        const uint32_t Bbs = sb + OFF_B + (c & 3) * BSTAGE_B;
#pragma unroll
        for (int ks = 0; ks < 4; ks++) {
            const int ga = ks * 2 + gsel;
            uint32_t a[4][4];
#pragma unroll
            for (int mi = 0; mi < 4; mi++) {
                int row = m_base + mi * 16 + rowsel;
                ldsm_x4(a[mi], Abs + row * 128 + ((ga ^ (row & 7)) << 4));
            }
            const int krow = ks * 16 + bksel;
            uint32_t b[4][4];
#pragma unroll
            for (int nq = 0; nq < 4; nq++) {
                int g = wn * 8 + nq * 2 + bgsel;
                ldsm_x4_t(b[nq], Bbs + krow * 512 + ((g ^ (krow & 7)) << 4));
            }
#pragma unroll
            for (int mi = 0; mi < 4; mi++)
#pragma unroll
                for (int nq = 0; nq < 4; nq++) {
                    mma_f16(acc[mi][2 * nq + 0], a[mi], b[nq][0], b[nq][1]);
                    mma_f16(acc[mi][2 * nq + 1], a[mi], b[nq][2], b[nq][3]);
                }
        }
    }

    // ---- epilogue: bias (+gelu via erff) + store ----
    const int lr = lane >> 2;
    const int lc = (lane & 3) * 2;
    float2 bv[8];
#pragma unroll
    for (int ni = 0; ni < 8; ni++) {
        int col = n0 + n_base + ni * 8 + lc;
        const float* bp = bias + (size_t)e * Ntot + col;
        bv[ni] = make_float2(bp[0], bp[1]);
    }
#pragma unroll
    for (int mi = 0; mi < 4; mi++) {
        int r0 = m0 + m_base + mi * 16 + lr;
        int r1 = r0 + 8;
        bool v0 = r0 < cnt, v1 = r1 < cnt;
        OutT* o0 = Out + (size_t)(off + r0) * Ntot + n0 + n_base + lc;
        OutT* o1 = Out + (size_t)(off + r1) * Ntot + n0 + n_base + lc;
#pragma unroll
        for (int ni = 0; ni < 8; ni++) {
            if (v0) {
                float x0 = acc[mi][ni][0] + bv[ni].x;
                float x1 = acc[mi][ni][1] + bv[ni].y;
                if (DOGELU) { x0 = gelu_erf(x0); x1 = gelu_erf(x1); }
                if (sizeof(OutT) == 2)
                    *reinterpret_cast<__half2*>(o0 + ni * 8) = __floats2half2_rn(x0, x1);
                else
                    *reinterpret_cast<float2*>(o0 + ni * 8) = make_float2(x0, x1);
            }
            if (v1) {
                float x2 = acc[mi][ni][2] + bv[ni].x;
                float x3 = acc[mi][ni][3] + bv[ni].y;
                if (DOGELU) { x2 = gelu_erf(x2); x3 = gelu_erf(x3); }
                if (sizeof(OutT) == 2)
                    *reinterpret_cast<__half2*>(o1 + ni * 8) = __floats2half2_rn(x2, x3);
                else
                    *reinterpret_cast<float2*>(o1 + ni * 8) = make_float2(x2, x3);
            }
        }
    }
}

// ---------------- combine: out[t] = w0*eo[s0] + w1*eo[s1] ------------------
__global__ void combine_kernel(float* __restrict__ out) {
    int t = blockIdx.x;
    int s0 = g_slot_of[t * 2 + 0], s1 = g_slot_of[t * 2 + 1];
    float w0 = g_topw[t * 2 + 0], w1 = g_topw[t * 2 + 1];
    const float4* a = reinterpret_cast<const float4*>(g_eo + (size_t)s0 * DDIM);
    const float4* b = reinterpret_cast<const float4*>(g_eo + (size_t)s1 * DDIM);
    float4* o = reinterpret_cast<float4*>(out + (size_t)t * DDIM);
    for (int i = threadIdx.x; i < DDIM / 4; i += blockDim.x) {
        float4 va = a[i], vb = b[i];
        o[i] = make_float4(w0 * va.x + w1 * vb.x, w0 * va.y + w1 * vb.y,
                           w0 * va.z + w1 * vb.z, w0 * va.w + w1 * vb.w);
    }
}

// ---------------- launch ----------------------------------------------------
extern "C" void kernel_launch(void* const* d_in, const int* in_sizes, int n_in,
                              void* d_out, int out_size) {
    const float* x  = (const float*)d_in[0];
    const float* Wg = (const float*)d_in[1];
    const float* bg = (const float*)d_in[2];
    const float* W1 = (const float*)d_in[3];
    const float* b1 = (const float*)d_in[4];
    const float* W2 = (const float*)d_in[5];
    const float* b2 = (const float*)d_in[6];
    float* out = (float*)d_out;

    void *p_hh, *p_eo, *p_xh, *p_w1h, *p_w2h;
    cudaGetSymbolAddress(&p_hh,  g_hh);
    cudaGetSymbolAddress(&p_eo,  g_eo);
    cudaGetSymbolAddress(&p_xh,  g_xh);
    cudaGetSymbolAddress(&p_w1h, g_w1h);
    cudaGetSymbolAddress(&p_w2h, g_w2h);

    cudaFuncSetAttribute(moe_gemm<DDIM, true,  true,  __half>,
                         cudaFuncAttributeMaxDynamicSharedMemorySize, SM_BYTES);
    cudaFuncSetAttribute(moe_gemm<HDIM, false, false, float>,
                         cudaFuncAttributeMaxDynamicSharedMemorySize, SM_BYTES);

    reset_kernel<<<1, 32>>>();
    gate_kernel<<<N_TOK, 32>>>(x, Wg, bg);
    offsets_kernel<<<1, 32>>>();
    scatter_kernel<<<(N_TOK + 255) / 256, 256>>>();
    conv_half_kernel<<<((size_t)N_TOK * DDIM / 8) / 256, 256>>>(x, (__half*)p_xh);
    conv_half_kernel<<<((size_t)NEXP * DDIM * HDIM / 8) / 256, 256>>>(W1, (__half*)p_w1h);
    conv_half_kernel<<<((size_t)NEXP * DDIM * HDIM / 8) / 256, 256>>>(W2, (__half*)p_w2h);
    // GEMM1: h = fp16(gelu(x[perm] @ W1 + b1))   K=1024, N=4096
    moe_gemm<DDIM, true, true, __half>
        <<<dim3(32, HDIM / 256, NEXP), 256, SM_BYTES>>>(
        (const __half*)p_xh, (const __half*)p_w1h, b1, (__half*)p_hh, HDIM);
    // GEMM2: eo = h @ W2 + b2                    K=4096, N=1024
    moe_gemm<HDIM, false, false, float>
        <<<dim3(32, DDIM / 256, NEXP), 256, SM_BYTES>>>(
        (const __half*)p_hh, (const __half*)p_w2h, b2, (float*)p_eo, DDIM);
    combine_kernel<<<N_TOK, 256>>>(out);
}

// round 11
// speedup vs baseline: 1.7953x; 1.0174x over previous
#include <cuda_runtime.h>
#include <cuda_fp16.h>
#include <math.h>
#include <stdint.h>

#define N_TOK 4096      // B*T
#define DDIM  1024
#define HDIM  4096
#define NEXP  8
#define NSLOT (N_TOK * 2)

// ---------------- scratch (static device globals; no cudaMalloc) ----------
__device__ __half g_hh[(size_t)NSLOT * HDIM];         // 64 MB : gelu out (fp16)
__device__ float  g_eo[(size_t)NSLOT * DDIM];         // 32 MB : expert out (fp32)
__device__ __half g_xh[(size_t)N_TOK * DDIM];         //  8 MB : x (fp16)
__device__ __half g_w1h[(size_t)NEXP * DDIM * HDIM];  // 64 MB : W1 fp16
__device__ __half g_w2h[(size_t)NEXP * DDIM * HDIM];  // 64 MB : W2 fp16
__device__ int   g_perm[NSLOT];
__device__ int   g_slot_of[NSLOT];
__device__ int   g_tope[NSLOT];
__device__ float g_topw[NSLOT];
__device__ int   g_cnt[NEXP];
__device__ int   g_off[NEXP];
__device__ int   g_cur[NEXP];

// ======================= PTX helpers (compute_103-safe) ====================
__device__ __forceinline__ uint32_t smem_u32(const void* p) {
    uint32_t a;
    asm("{ .reg .u64 t; cvta.to.shared.u64 t, %1; cvt.u32.u64 %0, t; }"
        : "=r"(a) : "l"(p));
    return a;
}
__device__ __forceinline__ void cp_async16(uint32_t dst, const void* src, uint32_t sz) {
    asm volatile("cp.async.ca.shared.global [%0], [%1], 16, %2;"
                 :: "r"(dst), "l"(src), "r"(sz) : "memory");
}
#define CP_COMMIT() asm volatile("cp.async.commit_group;" ::: "memory")
#define CP_WAIT(n)  asm volatile("cp.async.wait_group %0;" :: "n"(n) : "memory")

__device__ __forceinline__ void ldsm_x4(uint32_t* r, uint32_t addr) {
    asm volatile("ldmatrix.sync.aligned.m8n8.x4.shared.b16 {%0,%1,%2,%3}, [%4];"
                 : "=r"(r[0]), "=r"(r[1]), "=r"(r[2]), "=r"(r[3]) : "r"(addr));
}
__device__ __forceinline__ void ldsm_x4_t(uint32_t* r, uint32_t addr) {
    asm volatile("ldmatrix.sync.aligned.m8n8.x4.trans.shared.b16 {%0,%1,%2,%3}, [%4];"
                 : "=r"(r[0]), "=r"(r[1]), "=r"(r[2]), "=r"(r[3]) : "r"(addr));
}
__device__ __forceinline__ void mma_f16(float* d, const uint32_t* a,
                                        uint32_t b0, uint32_t b1) {
    asm volatile(
        "mma.sync.aligned.m16n8k16.row.col.f32.f16.f16.f32 "
        "{%0,%1,%2,%3}, {%4,%5,%6,%7}, {%8,%9}, {%0,%1,%2,%3};"
        : "+f"(d[0]), "+f"(d[1]), "+f"(d[2]), "+f"(d[3])
        : "r"(a[0]), "r"(a[1]), "r"(a[2]), "r"(a[3]), "r"(b0), "r"(b1));
}
// exact gelu via erff (no erfc range-reduction/exp path)
__device__ __forceinline__ float gelu_erf(float v) {
    return 0.5f * v * (1.0f + erff(v * 0.70710678118654752f));
}

// ======================= small kernels ======================================
__global__ void reset_kernel() {
    int i = threadIdx.x;
    if (i < NEXP) { g_cnt[i] = 0; g_cur[i] = 0; }
}

// 8 warps per block, one token per warp
__global__ void gate_kernel(const float* __restrict__ x,
                            const float* __restrict__ Wg,
                            const float* __restrict__ bg) {
    int wid = threadIdx.x >> 5;
    int lane = threadIdx.x & 31;
    int t = blockIdx.x * 8 + wid;
    if (t >= N_TOK) return;
    const float* xr = x + (size_t)t * DDIM;
    float p[NEXP];
#pragma unroll
    for (int e = 0; e < NEXP; e++) p[e] = 0.f;
    for (int d = lane; d < DDIM; d += 32) {
        float xv = xr[d];
        const float4* w4 = reinterpret_cast<const float4*>(Wg + (size_t)d * NEXP);
        float4 a = w4[0], b = w4[1];
        p[0] += xv * a.x; p[1] += xv * a.y; p[2] += xv * a.z; p[3] += xv * a.w;
        p[4] += xv * b.x; p[5] += xv * b.y; p[6] += xv * b.z; p[7] += xv * b.w;
    }
#pragma unroll
    for (int off = 16; off; off >>= 1)
#pragma unroll
        for (int e = 0; e < NEXP; e++)
            p[e] += __shfl_xor_sync(0xffffffffu, p[e], off);
    if (lane == 0) {
#pragma unroll
        for (int e = 0; e < NEXP; e++) p[e] += bg[e];
        int i0 = 0;
#pragma unroll
        for (int e = 1; e < NEXP; e++) if (p[e] > p[i0]) i0 = e;
        int i1 = (i0 == 0) ? 1 : 0;
#pragma unroll
        for (int e = 0; e < NEXP; e++)
            if (e != i0 && p[e] > p[i1]) i1 = e;
        float e1 = expf(p[i1] - p[i0]);
        float w0 = 1.0f / (1.0f + e1);
        float w1 = e1 / (1.0f + e1);
        g_tope[t * 2 + 0] = i0;  g_tope[t * 2 + 1] = i1;
        g_topw[t * 2 + 0] = w0;  g_topw[t * 2 + 1] = w1;
        atomicAdd(&g_cnt[i0], 1);
        atomicAdd(&g_cnt[i1], 1);
    }
}

__global__ void offsets_kernel() {
    if (threadIdx.x == 0) {
        int acc = 0;
        for (int e = 0; e < NEXP; e++) { g_off[e] = acc; acc += g_cnt[e]; }
    }
}

__global__ void scatter_kernel() {
    int t = blockIdx.x * blockDim.x + threadIdx.x;
    if (t >= N_TOK) return;
#pragma unroll
    for (int k = 0; k < 2; k++) {
        int e = g_tope[t * 2 + k];
        int pos = g_off[e] + atomicAdd(&g_cur[e], 1);
        g_perm[pos] = t;
        g_slot_of[t * 2 + k] = pos;
    }
}

// ---------------- fp32 -> fp16 elementwise (8 elems/thread) ----------------
__global__ void conv_half_kernel(const float* __restrict__ in,
                                 __half* __restrict__ out) {
    size_t i = (size_t)(blockIdx.x * blockDim.x + threadIdx.x) * 8;
    float4 v0 = *reinterpret_cast<const float4*>(in + i);
    float4 v1 = *reinterpret_cast<const float4*>(in + i + 4);
    __half2 h[4];
    h[0] = __floats2half2_rn(v0.x, v0.y);
    h[1] = __floats2half2_rn(v0.z, v0.w);
    h[2] = __floats2half2_rn(v1.x, v1.y);
    h[3] = __floats2half2_rn(v1.z, v1.w);
    *reinterpret_cast<uint4*>(out + i) = *reinterpret_cast<uint4*>(h);
}

// ======================= fp16 mma.sync grouped GEMM =========================
// CTA tile 128(M) x 256(N), k-chunk 64, 8 warps (2m x 4n), warp tile 64x64.
// 4-stage cp.async pipeline, ONE barrier per chunk. (unchanged from R10)
#define ASTAGE_B 16384
#define BSTAGE_B 32768
#define OFF_A    1024
#define OFF_B    (OFF_A + 4 * ASTAGE_B)        // 66560
#define SM_BYTES (OFF_B + 4 * BSTAGE_B)        // 197632

template <int KDIM, bool GATHER, bool DOGELU, typename OutT>
__global__ __launch_bounds__(256) void moe_gemm(
    const __half* __restrict__ Ah, const __half* __restrict__ Bh,
    const float* __restrict__ bias, OutT* __restrict__ Out, int Ntot) {
    extern __shared__ char smem[];
    const int e = blockIdx.z;
    const int cnt = g_cnt[e];
    const int m0 = blockIdx.x * 128;
    if (m0 >= cnt) return;
    const int off = g_off[e];
    const int n0 = blockIdx.y * 256;
    const __half* Bte = Bh + (size_t)e * KDIM * Ntot;   // [K][Ntot]

    const uint32_t sb = smem_u32(smem);
    const int tid = threadIdx.x;
    const int wid = tid >> 5, lane = tid & 31;
    const int wm = wid & 1, wn = wid >> 1;
    const int m_base = wm * 64, n_base = wn * 64;

    int* rowtok = (int*)smem;
    if (GATHER && tid < 128) {
        int r = m0 + tid;
        rowtok[tid] = (r < cnt) ? g_perm[off + r] : -1;
    }
    __syncthreads();

    constexpr int NC = KDIM / 64;

    auto load_chunk = [&](int c) {
        const int s = c & 3;
        const int k0 = c * 64;
        const uint32_t Abs = sb + OFF_A + s * ASTAGE_B;
        const uint32_t Bbs = sb + OFF_B + s * BSTAGE_B;
#pragma unroll
        for (int f = 0; f < 4; f++) {
            int id = tid + f * 256;
            int row = id >> 3, g = id & 7;
            uint32_t sz = 16;
            const char* src;
            if (GATHER) {
                int tok = rowtok[row];
                if (tok < 0) { sz = 0; tok = 0; }
                src = (const char*)(Ah + (size_t)tok * KDIM + k0) + g * 16;
            } else {
                int mr = m0 + row;
                if (mr >= cnt) { sz = 0; mr = 0; }
                src = (const char*)(Ah + (size_t)(off + mr) * KDIM + k0) + g * 16;
            }
            cp_async16(Abs + row * 128 + ((g ^ (row & 7)) << 4), src, sz);
        }
#pragma unroll
        for (int f = 0; f < 8; f++) {
            int id = tid + f * 256;
            int krow = id >> 5, g = id & 31;
            const char* src =
                (const char*)(Bte + (size_t)(k0 + krow) * Ntot + n0) + g * 16;
            cp_async16(Bbs + krow * 512 + ((g ^ (krow & 7)) << 4), src, 16);
        }
        CP_COMMIT();
    };

    float acc[4][8][4];
#pragma unroll
    for (int mi = 0; mi < 4; mi++)
#pragma unroll
        for (int ni = 0; ni < 8; ni++)
#pragma unroll
            for (int q = 0; q < 4; q++) acc[mi][ni][q] = 0.f;

    load_chunk(0);
    load_chunk(1);
    load_chunk(2);

    const int rowsel = ((lane >> 3) & 1) * 8 + (lane & 7);
    const int gsel = (lane >> 4);
    const int bksel = lane & 15;
    const int bgsel = lane >> 4;

#pragma unroll 1
    for (int c = 0; c < NC; c++) {
        if (c + 2 < NC)      { CP_WAIT(2); }
        else if (c + 1 < NC) { CP_WAIT(1); }
        else                 { CP_WAIT(0); }
        __syncthreads();
        if (c + 3 < NC) load_chunk(c + 3);

        const uint32_t Abs = sb + OFF_A + (c & 3) * ASTAGE_B;
        const uint32_t Bbs = sb + OFF_B + (c & 3) * BSTAGE_B;
#pragma unroll
        for (int ks = 0; ks < 4; ks++) {
            const int ga = ks * 2 + gsel;
            uint32_t a[4][4];
#pragma unroll
            for (int mi = 0; mi < 4; mi++) {
                int row = m_base + mi * 16 + rowsel;
                ldsm_x4(a[mi], Abs + row * 128 + ((ga ^ (row & 7)) << 4));
            }
            const int krow = ks * 16 + bksel;
            uint32_t b[4][4];
#pragma unroll
            for (int nq = 0; nq < 4; nq++) {
                int g = wn * 8 + nq * 2 + bgsel;
                ldsm_x4_t(b[nq], Bbs + krow * 512 + ((g ^ (krow & 7)) << 4));
            }
#pragma unroll
            for (int mi = 0; mi < 4; mi++)
#pragma unroll
                for (int nq = 0; nq < 4; nq++) {
                    mma_f16(acc[mi][2 * nq + 0], a[mi], b[nq][0], b[nq][1]);
                    mma_f16(acc[mi][2 * nq + 1], a[mi], b[nq][2], b[nq][3]);
                }
        }
    }

    // ---- epilogue: bias (+gelu via erff) + store ----
    const int lr = lane >> 2;
    const int lc = (lane & 3) * 2;
    float2 bv[8];
#pragma unroll
    for (int ni = 0; ni < 8; ni++) {
        int col = n0 + n_base + ni * 8 + lc;
        const float* bp = bias + (size_t)e * Ntot + col;
        bv[ni] = make_float2(bp[0], bp[1]);
    }
#pragma unroll
    for (int mi = 0; mi < 4; mi++) {
        int r0 = m0 + m_base + mi * 16 + lr;
        int r1 = r0 + 8;
        bool v0 = r0 < cnt, v1 = r1 < cnt;
        OutT* o0 = Out + (size_t)(off + r0) * Ntot + n0 + n_base + lc;
        OutT* o1 = Out + (size_t)(off + r1) * Ntot + n0 + n_base + lc;
#pragma unroll
        for (int ni = 0; ni < 8; ni++) {
            if (v0) {
                float x0 = acc[mi][ni][0] + bv[ni].x;
                float x1 = acc[mi][ni][1] + bv[ni].y;
                if (DOGELU) { x0 = gelu_erf(x0); x1 = gelu_erf(x1); }
                if (sizeof(OutT) == 2)
                    *reinterpret_cast<__half2*>(o0 + ni * 8) = __floats2half2_rn(x0, x1);
                else
                    *reinterpret_cast<float2*>(o0 + ni * 8) = make_float2(x0, x1);
            }
            if (v1) {
                float x2 = acc[mi][ni][2] + bv[ni].x;
                float x3 = acc[mi][ni][3] + bv[ni].y;
                if (DOGELU) { x2 = gelu_erf(x2); x3 = gelu_erf(x3); }
                if (sizeof(OutT) == 2)
                    *reinterpret_cast<__half2*>(o1 + ni * 8) = __floats2half2_rn(x2, x3);
                else
                    *reinterpret_cast<float2*>(o1 + ni * 8) = make_float2(x2, x3);
            }
        }
    }
}

// ---------------- combine: out[t] = w0*eo[s0] + w1*eo[s1] ------------------
__global__ void combine_kernel(float* __restrict__ out) {
    int t = blockIdx.x;
    int s0 = g_slot_of[t * 2 + 0], s1 = g_slot_of[t * 2 + 1];
    float w0 = g_topw[t * 2 + 0], w1 = g_topw[t * 2 + 1];
    const float4* a = reinterpret_cast<const float4*>(g_eo + (size_t)s0 * DDIM);
    const float4* b = reinterpret_cast<const float4*>(g_eo + (size_t)s1 * DDIM);
    float4* o = reinterpret_cast<float4*>(out + (size_t)t * DDIM);
    for (int i = threadIdx.x; i < DDIM / 4; i += blockDim.x) {
        float4 va = a[i], vb = b[i];
        o[i] = make_float4(w0 * va.x + w1 * vb.x, w0 * va.y + w1 * vb.y,
                           w0 * va.z + w1 * vb.z, w0 * va.w + w1 * vb.w);
    }
}

// ---------------- launch ----------------------------------------------------
// Side-stream fork/join (host-side resources only; created on the first,
// non-captured, correctness call; identical work enqueued every call).
struct AuxRes {
    cudaStream_t s2;
    cudaEvent_t fork, w1, w2;
    AuxRes() {
        cudaStreamCreateWithFlags(&s2, cudaStreamNonBlocking);
        cudaEventCreateWithFlags(&fork, cudaEventDisableTiming);
        cudaEventCreateWithFlags(&w1, cudaEventDisableTiming);
        cudaEventCreateWithFlags(&w2, cudaEventDisableTiming);
    }
};

extern "C" void kernel_launch(void* const* d_in, const int* in_sizes, int n_in,
                              void* d_out, int out_size) {
    const float* x  = (const float*)d_in[0];
    const float* Wg = (const float*)d_in[1];
    const float* bg = (const float*)d_in[2];
    const float* W1 = (const float*)d_in[3];
    const float* b1 = (const float*)d_in[4];
    const float* W2 = (const float*)d_in[5];
    const float* b2 = (const float*)d_in[6];
    float* out = (float*)d_out;

    static AuxRes R;   // magic-static init on first (correctness) call

    void *p_hh, *p_eo, *p_xh, *p_w1h, *p_w2h;
    cudaGetSymbolAddress(&p_hh,  g_hh);
    cudaGetSymbolAddress(&p_eo,  g_eo);
    cudaGetSymbolAddress(&p_xh,  g_xh);
    cudaGetSymbolAddress(&p_w1h, g_w1h);
    cudaGetSymbolAddress(&p_w2h, g_w2h);

    cudaFuncSetAttribute(moe_gemm<DDIM, true,  true,  __half>,
                         cudaFuncAttributeMaxDynamicSharedMemorySize, SM_BYTES);
    cudaFuncSetAttribute(moe_gemm<HDIM, false, false, float>,
                         cudaFuncAttributeMaxDynamicSharedMemorySize, SM_BYTES);

    // ---- fork: weight conversions on side stream ----
    cudaEventRecord(R.fork, 0);
    cudaStreamWaitEvent(R.s2, R.fork, 0);
    conv_half_kernel<<<((size_t)NEXP * DDIM * HDIM / 8) / 256, 256, 0, R.s2>>>(
        W1, (__half*)p_w1h);
    cudaEventRecord(R.w1, R.s2);
    conv_half_kernel<<<((size_t)NEXP * DDIM * HDIM / 8) / 256, 256, 0, R.s2>>>(
        W2, (__half*)p_w2h);
    cudaEventRecord(R.w2, R.s2);

    // ---- main stream: gating chain + x conversion ----
    reset_kernel<<<1, 32>>>();
    gate_kernel<<<N_TOK / 8, 256>>>(x, Wg, bg);
    offsets_kernel<<<1, 32>>>();
    scatter_kernel<<<(N_TOK + 255) / 256, 256>>>();
    conv_half_kernel<<<((size_t)N_TOK * DDIM / 8) / 256, 256>>>(x, (__half*)p_xh);

    // ---- join W1, GEMM1 ----
    cudaStreamWaitEvent(0, R.w1, 0);
    moe_gemm<DDIM, true, true, __half>
        <<<dim3(32, HDIM / 256, NEXP), 256, SM_BYTES>>>(
        (const __half*)p_xh, (const __half*)p_w1h, b1, (__half*)p_hh, HDIM);

    // ---- join W2, GEMM2 ----
    cudaStreamWaitEvent(0, R.w2, 0);
    moe_gemm<HDIM, false, false, float>
        <<<dim3(32, DDIM / 256, NEXP), 256, SM_BYTES>>>(
        (const __half*)p_hh, (const __half*)p_w2h, b2, (float*)p_eo, DDIM);

    combine_kernel<<<N_TOK, 256>>>(out);
}